// round 3
// baseline (speedup 1.0000x reference)
#include <cuda_runtime.h>

#define BB   4
#define NNN  2048
#define CCC  256
#define HHH  8
#define DHH  32
#define WINW 16
#define SCALE 0.17677669529663687f   // 32^-0.5

// -------- scratch (device globals; no allocations allowed) --------
__device__ float g_qkv[3LL * BB * HHH * NNN * DHH];   // [3][B][H][N][32]  24 MB
__device__ float g_comb[(long long)BB * NNN * CCC];   // [B][N][C]          8 MB

// ============================================================
// Kernel 1: QKV GEMM.  X[8192,256] @ W[256,768] -> scatter to g_qkv
// BM=64 BN=64 BK=16, 256 threads, 4x4 microtile
// ============================================================
__global__ __launch_bounds__(256) void qkv_gemm_kernel(const float* __restrict__ X,
                                                       const float* __restrict__ W) {
    __shared__ float Xs[16 * 68];   // Xs[k][m], padded row 68
    __shared__ float Ws[16 * 64];   // Ws[k][n]
    const int t  = threadIdx.x;
    const int tx = t & 15, ty = t >> 4;
    const int m0 = blockIdx.y * 64;
    const int n0 = blockIdx.x * 64;

    float acc[4][4] = {};

    for (int k0 = 0; k0 < CCC; k0 += 16) {
        {
            int kk = t & 15, mloc = t >> 4;
            #pragma unroll
            for (int r = 0; r < 4; r++) {
                int m = mloc + r * 16;
                Xs[kk * 68 + m] = X[(long long)(m0 + m) * CCC + k0 + kk];
            }
        }
        {
            int nn = t & 63, kk = t >> 6;
            #pragma unroll
            for (int r = 0; r < 4; r++)
                Ws[(kk + r * 4) * 64 + nn] = W[(long long)(k0 + kk + r * 4) * 768 + n0 + nn];
        }
        __syncthreads();
        #pragma unroll
        for (int kk = 0; kk < 16; kk++) {
            float4 a = *(const float4*)(Xs + kk * 68 + ty * 4);
            float4 b = *(const float4*)(Ws + kk * 64 + tx * 4);
            acc[0][0] += a.x * b.x; acc[0][1] += a.x * b.y; acc[0][2] += a.x * b.z; acc[0][3] += a.x * b.w;
            acc[1][0] += a.y * b.x; acc[1][1] += a.y * b.y; acc[1][2] += a.y * b.z; acc[1][3] += a.y * b.w;
            acc[2][0] += a.z * b.x; acc[2][1] += a.z * b.y; acc[2][2] += a.z * b.z; acc[2][3] += a.z * b.w;
            acc[3][0] += a.w * b.x; acc[3][1] += a.w * b.y; acc[3][2] += a.w * b.z; acc[3][3] += a.w * b.w;
        }
        __syncthreads();
    }
    #pragma unroll
    for (int ii = 0; ii < 4; ii++) {
        int row = m0 + ty * 4 + ii;
        int b   = row >> 11;          // /2048
        int n   = row & 2047;
        #pragma unroll
        for (int jj = 0; jj < 4; jj++) {
            int col = n0 + tx * 4 + jj;
            int t3  = col >> 8;       // 0..2  (q/k/v)
            int rem = col & 255;
            int h   = rem >> 5;
            int d   = rem & 31;
            g_qkv[((((long long)t3 * BB + b) * HHH + h) * NNN + n) * DHH + d] = acc[ii][jj];
        }
    }
}

// ============================================================
// Kernel 2: fused global attention per (b,h, 16-row block)
// smem: S[16][2050] + qs[32][17] + (kt[32][66] | vt[128][32]) + stats
// ============================================================
#define S_STRIDE 2050
#define QS_OFF   (16 * S_STRIDE)           // 32800
#define KT_OFF   (QS_OFF + 32 * 17)        // 33344  (also vt)
#define ST_OFF   (KT_OFF + 4096)           // 37440
#define ATTN_SMEM ((ST_OFF + 32) * 4)      // 149888 bytes

__global__ __launch_bounds__(256) void attn_global_kernel(float* __restrict__ out_w) {
    extern __shared__ float sm[];
    float* S    = sm;
    float* qs   = sm + QS_OFF;     // qs[d][i], pad 17
    float* kt   = sm + KT_OFF;     // kt[d][c], pad 66
    float* vt   = sm + KT_OFF;     // vt[k][d], 128x32 (aliases kt)
    float* rinv = sm + ST_OFF;

    const int t  = threadIdx.x;
    const int bh = blockIdx.y;                  // b*8 + h
    const int i0 = blockIdx.x * 16;
    const float* Q = g_qkv + (long long)bh * NNN * DHH;
    const float* K = g_qkv + ((long long)BB * HHH + bh) * NNN * DHH;
    const float* V = g_qkv + ((long long)2 * BB * HHH + bh) * NNN * DHH;

    // load q block transposed: qs[d][i]
    {
        int d = t & 31, il = t >> 5;
        #pragma unroll
        for (int r = 0; r < 2; r++) {
            int i = il + r * 8;
            qs[d * 17 + i] = Q[(long long)(i0 + i) * DHH + d];
        }
    }

    const int tx = t & 31, ty = t >> 5;

    // ---------- Phase 1: S = scale * Q Kt, kept in smem ----------
    for (int kj0 = 0; kj0 < NNN; kj0 += 64) {
        __syncthreads();
        {
            int d = t & 31, cl = t >> 5;
            #pragma unroll
            for (int r = 0; r < 8; r++) {
                int c = cl + r * 8;
                kt[d * 66 + c] = K[(long long)(kj0 + c) * DHH + d];
            }
        }
        __syncthreads();
        float a00 = 0.f, a01 = 0.f, a10 = 0.f, a11 = 0.f;
        #pragma unroll
        for (int d = 0; d < 32; d++) {
            float q0 = qs[d * 17 + 2 * ty];
            float q1 = qs[d * 17 + 2 * ty + 1];
            float2 bb = *(const float2*)(kt + d * 66 + 2 * tx);
            a00 += q0 * bb.x; a01 += q0 * bb.y;
            a10 += q1 * bb.x; a11 += q1 * bb.y;
        }
        float2 v0 = make_float2(a00 * SCALE, a01 * SCALE);
        float2 v1 = make_float2(a10 * SCALE, a11 * SCALE);
        *(float2*)(S + (2 * ty)     * S_STRIDE + kj0 + 2 * tx) = v0;
        *(float2*)(S + (2 * ty + 1) * S_STRIDE + kj0 + 2 * tx) = v1;
    }
    __syncthreads();

    // ---------- Phase 2: softmax (16 lanes per row) ----------
    {
        int row = t >> 4, lane = t & 15;
        float m = -1e30f;
        for (int j = lane; j < NNN; j += 16) m = fmaxf(m, S[row * S_STRIDE + j]);
        #pragma unroll
        for (int o = 8; o; o >>= 1) m = fmaxf(m, __shfl_xor_sync(0xffffffffu, m, o, 16));
        float ssum = 0.f;
        for (int j = lane; j < NNN; j += 16) {
            float e = __expf(S[row * S_STRIDE + j] - m);
            S[row * S_STRIDE + j] = e;
            ssum += e;
        }
        #pragma unroll
        for (int o = 8; o; o >>= 1) ssum += __shfl_xor_sync(0xffffffffu, ssum, o, 16);
        if (lane == 0) rinv[row] = 1.0f / ssum;
    }
    __syncthreads();

    // ---------- Phase 2b: normalize + write attn weights (coalesced) ----------
    {
        float* wbase = out_w + (long long)bh * NNN * NNN + (long long)i0 * NNN;
        for (int i = 0; i < 16; i++) {
            float inv = rinv[i];
            for (int j = t; j < NNN; j += 256) {
                float v = S[i * S_STRIDE + j] * inv;
                S[i * S_STRIDE + j] = v;
                wbase[(long long)i * NNN + j] = v;
            }
        }
    }

    // ---------- Phase 3: O = attn @ V ----------
    float2 acc = make_float2(0.f, 0.f);
    const int oi = t >> 4, od = t & 15;
    for (int vj0 = 0; vj0 < NNN; vj0 += 128) {
        __syncthreads();
        {
            const float4* src = (const float4*)(V + (long long)vj0 * DHH);
            float4* dst = (float4*)vt;
            #pragma unroll
            for (int r = 0; r < 4; r++) dst[t + r * 256] = src[t + r * 256];
        }
        __syncthreads();
        #pragma unroll 4
        for (int k = 0; k < 128; k++) {
            float s = S[oi * S_STRIDE + vj0 + k];
            float2 vv = *(const float2*)(vt + k * 32 + 2 * od);
            acc.x += s * vv.x;
            acc.y += s * vv.y;
        }
    }
    {
        int b = bh >> 3, h = bh & 7;
        long long off = ((long long)b * NNN + i0 + oi) * CCC + h * DHH + 2 * od;
        *(float2*)(g_comb + off) = acc;
    }
}

// ============================================================
// Kernel 3: local window attention, accumulates into g_comb
// one window (16x32) per CTA, 128 threads
// ============================================================
__global__ __launch_bounds__(128) void local_attn_kernel() {
    __shared__ float ql[16 * 33], kl[16 * 33], vl[16 * 33], sl[16 * 17];
    const int t  = threadIdx.x;
    const int w  = blockIdx.x;
    const int bh = blockIdx.y;
    const float* Qp = g_qkv + ((long long)bh * NNN + w * WINW) * DHH;
    const float* Kp = g_qkv + (((long long)BB * HHH + bh) * NNN + w * WINW) * DHH;
    const float* Vp = g_qkv + (((long long)2 * BB * HHH + bh) * NNN + w * WINW) * DHH;

    #pragma unroll
    for (int r = 0; r < 4; r++) {
        int idx = t + r * 128;
        int i = idx >> 5, d = idx & 31;
        ql[i * 33 + d] = Qp[idx];
        kl[i * 33 + d] = Kp[idx];
        vl[i * 33 + d] = Vp[idx];
    }
    __syncthreads();
    #pragma unroll
    for (int r = 0; r < 2; r++) {
        int p = t + r * 128;
        int i = p >> 4, j = p & 15;
        float a = 0.f;
        #pragma unroll
        for (int d = 0; d < 32; d++) a += ql[i * 33 + d] * kl[j * 33 + d];
        sl[i * 17 + j] = a * SCALE;
    }
    __syncthreads();
    if (t < 16) {
        float m = -1e30f;
        #pragma unroll
        for (int j = 0; j < 16; j++) m = fmaxf(m, sl[t * 17 + j]);
        float s = 0.f;
        #pragma unroll
        for (int j = 0; j < 16; j++) { float e = __expf(sl[t * 17 + j] - m); sl[t * 17 + j] = e; s += e; }
        float inv = 1.0f / s;
        #pragma unroll
        for (int j = 0; j < 16; j++) sl[t * 17 + j] *= inv;
    }
    __syncthreads();
    const int b = bh >> 3, h = bh & 7;
    float* cb = g_comb + ((long long)b * NNN + w * WINW) * CCC + h * DHH;
    #pragma unroll
    for (int r = 0; r < 4; r++) {
        int p = t + r * 128;
        int i = p >> 5, d = p & 31;
        float a = 0.f;
        #pragma unroll
        for (int j = 0; j < 16; j++) a += sl[i * 17 + j] * vl[j * 33 + d];
        cb[(long long)i * CCC + d] += a;
    }
}

// ============================================================
// Kernel 4: output projection.  g_comb[8192,256] @ Wp[256,256] + b -> out
// ============================================================
__global__ __launch_bounds__(256) void proj_gemm_kernel(const float* __restrict__ W,
                                                        const float* __restrict__ bias,
                                                        float* __restrict__ out) {
    __shared__ float Xs[16 * 68];
    __shared__ float Ws[16 * 64];
    const int t  = threadIdx.x;
    const int tx = t & 15, ty = t >> 4;
    const int m0 = blockIdx.y * 64;
    const int n0 = blockIdx.x * 64;

    float acc[4][4] = {};
    for (int k0 = 0; k0 < CCC; k0 += 16) {
        {
            int kk = t & 15, mloc = t >> 4;
            #pragma unroll
            for (int r = 0; r < 4; r++) {
                int m = mloc + r * 16;
                Xs[kk * 68 + m] = g_comb[(long long)(m0 + m) * CCC + k0 + kk];
            }
        }
        {
            int nn = t & 63, kk = t >> 6;
            #pragma unroll
            for (int r = 0; r < 4; r++)
                Ws[(kk + r * 4) * 64 + nn] = W[(long long)(k0 + kk + r * 4) * CCC + n0 + nn];
        }
        __syncthreads();
        #pragma unroll
        for (int kk = 0; kk < 16; kk++) {
            float4 a = *(const float4*)(Xs + kk * 68 + ty * 4);
            float4 b = *(const float4*)(Ws + kk * 64 + tx * 4);
            acc[0][0] += a.x * b.x; acc[0][1] += a.x * b.y; acc[0][2] += a.x * b.z; acc[0][3] += a.x * b.w;
            acc[1][0] += a.y * b.x; acc[1][1] += a.y * b.y; acc[1][2] += a.y * b.z; acc[1][3] += a.y * b.w;
            acc[2][0] += a.z * b.x; acc[2][1] += a.z * b.y; acc[2][2] += a.z * b.z; acc[2][3] += a.z * b.w;
            acc[3][0] += a.w * b.x; acc[3][1] += a.w * b.y; acc[3][2] += a.w * b.z; acc[3][3] += a.w * b.w;
        }
        __syncthreads();
    }
    #pragma unroll
    for (int ii = 0; ii < 4; ii++) {
        int row = m0 + ty * 4 + ii;
        #pragma unroll
        for (int jj = 0; jj < 4; jj++) {
            int col = n0 + tx * 4 + jj;
            out[(long long)row * CCC + col] = acc[ii][jj] + bias[col];
        }
    }
}

// ============================================================
extern "C" void kernel_launch(void* const* d_in, const int* in_sizes, int n_in,
                              void* d_out, int out_size) {
    const float* x     = (const float*)d_in[0];
    const float* Wqkv  = (const float*)d_in[1];
    const float* Wproj = (const float*)d_in[2];
    const float* bproj = (const float*)d_in[3];
    float* out   = (float*)d_out;
    float* out_w = out + (long long)BB * NNN * CCC;   // attn weights region

    cudaFuncSetAttribute(attn_global_kernel,
                         cudaFuncAttributeMaxDynamicSharedMemorySize, ATTN_SMEM);

    qkv_gemm_kernel<<<dim3(12, 128), 256>>>(x, Wqkv);
    attn_global_kernel<<<dim3(NNN / 16, BB * HHH), 256, ATTN_SMEM>>>(out_w);
    local_attn_kernel<<<dim3(NNN / WINW, BB * HHH), 128>>>();
    proj_gemm_kernel<<<dim3(CCC / 64, (BB * NNN) / 64), 256>>>(Wproj, bproj, out);
}

// round 4
// speedup vs baseline: 2.0346x; 2.0346x over previous
#include <cuda_runtime.h>

#define BB   4
#define NNN  2048
#define CCC  256
#define HHH  8
#define DHH  32
#define WINW 16
#define SCALE 0.17677669529663687f   // 32^-0.5

// -------- scratch (device globals; no allocations allowed) --------
__device__ float g_qkv[3LL * BB * HHH * NNN * DHH];   // [3][B][H][N][32]  24 MB
__device__ float g_comb[(long long)BB * NNN * CCC];   // [B][N][C]          8 MB

// ============================================================
// Kernel 1: QKV GEMM.  X[8192,256] @ W[256,768] -> scatter to g_qkv
// ============================================================
__global__ __launch_bounds__(256) void qkv_gemm_kernel(const float* __restrict__ X,
                                                       const float* __restrict__ W) {
    __shared__ float Xs[16 * 68];   // Xs[k][m]
    __shared__ float Ws[16 * 64];   // Ws[k][n]
    const int t  = threadIdx.x;
    const int tx = t & 15, ty = t >> 4;
    const int m0 = blockIdx.y * 64;
    const int n0 = blockIdx.x * 64;

    float acc[4][4] = {};

    for (int k0 = 0; k0 < CCC; k0 += 16) {
        {
            int kk = t & 15, mloc = t >> 4;
            #pragma unroll
            for (int r = 0; r < 4; r++) {
                int m = mloc + r * 16;
                Xs[kk * 68 + m] = X[(long long)(m0 + m) * CCC + k0 + kk];
            }
        }
        {
            int nn = t & 63, kk = t >> 6;
            #pragma unroll
            for (int r = 0; r < 4; r++)
                Ws[(kk + r * 4) * 64 + nn] = W[(long long)(k0 + kk + r * 4) * 768 + n0 + nn];
        }
        __syncthreads();
        #pragma unroll
        for (int kk = 0; kk < 16; kk++) {
            float4 a = *(const float4*)(Xs + kk * 68 + ty * 4);
            float4 b = *(const float4*)(Ws + kk * 64 + tx * 4);
            acc[0][0] += a.x * b.x; acc[0][1] += a.x * b.y; acc[0][2] += a.x * b.z; acc[0][3] += a.x * b.w;
            acc[1][0] += a.y * b.x; acc[1][1] += a.y * b.y; acc[1][2] += a.y * b.z; acc[1][3] += a.y * b.w;
            acc[2][0] += a.z * b.x; acc[2][1] += a.z * b.y; acc[2][2] += a.z * b.z; acc[2][3] += a.z * b.w;
            acc[3][0] += a.w * b.x; acc[3][1] += a.w * b.y; acc[3][2] += a.w * b.z; acc[3][3] += a.w * b.w;
        }
        __syncthreads();
    }
    #pragma unroll
    for (int ii = 0; ii < 4; ii++) {
        int row = m0 + ty * 4 + ii;
        int b   = row >> 11;
        int n   = row & 2047;
        #pragma unroll
        for (int jj = 0; jj < 4; jj++) {
            int col = n0 + tx * 4 + jj;
            int t3  = col >> 8;
            int rem = col & 255;
            int h   = rem >> 5;
            int d   = rem & 31;
            g_qkv[((((long long)t3 * BB + b) * HHH + h) * NNN + n) * DHH + d] = acc[ii][jj];
        }
    }
}

// ============================================================
// Kernel 2: fused global attention per (b,h, 16-row block)
//   Phase1: S = (q*scale)·K^T  -- 4x8 microtile, ks[c][33] untransposed
//   Phase2: row softmax stats; S holds UNNORMALIZED e
//   Phase2b: write normalized weights (float4) to gmem only
//   Phase3: O = e·V with 16-way split-k, then scale by 1/sum
// smem layout (floats):
//   S[16][2052], qs[16][33], rinv[16], ks 512*33 (alias: vt 256*33, red 16*513)
// ============================================================
#define SS        2052
#define QS_OFF    (16 * SS)                 // 32832
#define RINV_OFF  (QS_OFF + 16 * 33)        // 33360
#define KS_OFF    (RINV_OFF + 16)           // 33376
#define ATTN_FLOATS (KS_OFF + 512 * 33)     // 50272
#define ATTN_SMEM (ATTN_FLOATS * 4)         // 201088 bytes

__global__ __launch_bounds__(256) void attn_global_kernel(float* __restrict__ out_w) {
    extern __shared__ float sm[];
    float* S    = sm;
    float* qs   = sm + QS_OFF;     // qs[i][d] (scale folded in)
    float* rinv = sm + RINV_OFF;
    float* ks   = sm + KS_OFF;     // ks[c][33]
    float* vt   = sm + KS_OFF;     // vt[c][33]  (alias)
    float* red  = sm + KS_OFF;     // red[kg][513] (alias, after vt dead)

    const int t  = threadIdx.x;
    const int bh = blockIdx.y;
    const int i0 = blockIdx.x * 16;
    const float* Q = g_qkv + (long long)bh * NNN * DHH;
    const float* K = g_qkv + ((long long)BB * HHH + bh) * NNN * DHH;
    const float* V = g_qkv + ((long long)2 * BB * HHH + bh) * NNN * DHH;

    // ---- load q block (scale folded) ----
    #pragma unroll
    for (int r = 0; r < 2; r++) {
        int idx = t + r * 256;
        int i = idx >> 5, d = idx & 31;
        qs[i * 33 + d] = Q[(long long)(i0 + i) * DHH + d] * SCALE;
    }

    // ---------- Phase 1: S = q·K^T  (tiles of 512 cols) ----------
    {
        const int cg = t & 63, rg = t >> 6;
        for (int kj0 = 0; kj0 < NNN; kj0 += 512) {
            __syncthreads();
            // load K tile untransposed: ks[c][d], stride 33 (conflict-free scalar STS)
            #pragma unroll
            for (int r = 0; r < 16; r++) {
                int idx = t + r * 256;
                int c = idx >> 3, f4 = idx & 7;
                float4 kv4 = *(const float4*)(K + (long long)(kj0 + c) * DHH + f4 * 4);
                float* p = ks + c * 33 + f4 * 4;
                p[0] = kv4.x; p[1] = kv4.y; p[2] = kv4.z; p[3] = kv4.w;
            }
            __syncthreads();

            float acc[4][8] = {};
            #pragma unroll
            for (int d = 0; d < 32; d++) {
                float qv[4];
                #pragma unroll
                for (int r = 0; r < 4; r++) qv[r] = qs[(rg * 4 + r) * 33 + d];  // broadcast
                float kv[8];
                #pragma unroll
                for (int cc = 0; cc < 8; cc++) kv[cc] = ks[(cg + 64 * cc) * 33 + d];
                #pragma unroll
                for (int r = 0; r < 4; r++)
                    #pragma unroll
                    for (int cc = 0; cc < 8; cc++)
                        acc[r][cc] += qv[r] * kv[cc];
            }
            #pragma unroll
            for (int r = 0; r < 4; r++)
                #pragma unroll
                for (int cc = 0; cc < 8; cc++)
                    S[(rg * 4 + r) * SS + kj0 + cg + 64 * cc] = acc[r][cc];
        }
    }
    __syncthreads();

    // ---------- Phase 2: softmax stats; S := e (unnormalized) ----------
    {
        int row = t >> 4, lane = t & 15;
        float* Sr = S + row * SS;
        float m = -1e30f;
        #pragma unroll 8
        for (int i = 0; i < 32; i++) {
            float4 v = *(const float4*)(Sr + i * 64 + lane * 4);
            m = fmaxf(m, fmaxf(fmaxf(v.x, v.y), fmaxf(v.z, v.w)));
        }
        #pragma unroll
        for (int o = 8; o; o >>= 1) m = fmaxf(m, __shfl_xor_sync(0xffffffffu, m, o, 16));
        float ssum = 0.f;
        #pragma unroll 8
        for (int i = 0; i < 32; i++) {
            float4 v = *(float4*)(Sr + i * 64 + lane * 4);
            v.x = __expf(v.x - m); v.y = __expf(v.y - m);
            v.z = __expf(v.z - m); v.w = __expf(v.w - m);
            *(float4*)(Sr + i * 64 + lane * 4) = v;
            ssum += (v.x + v.y) + (v.z + v.w);
        }
        #pragma unroll
        for (int o = 8; o; o >>= 1) ssum += __shfl_xor_sync(0xffffffffu, ssum, o, 16);
        if (lane == 0) rinv[row] = 1.0f / ssum;
    }
    __syncthreads();

    // ---------- Phase 2b: write normalized weights to gmem (float4) ----------
    {
        float* wbase = out_w + (long long)bh * NNN * NNN + (long long)i0 * NNN;
        for (int i = 0; i < 16; i++) {
            float inv = rinv[i];
            #pragma unroll
            for (int r = 0; r < 2; r++) {
                int idx = t + r * 256;            // float4 index, 512 per row
                float4 v = *(const float4*)(S + i * SS + idx * 4);
                v.x *= inv; v.y *= inv; v.z *= inv; v.w *= inv;
                *(float4*)(wbase + (long long)i * NNN + idx * 4) = v;
            }
        }
    }

    // ---------- Phase 3: O = e·V  (16-way split-k, 4 rows x 8 dims / thread) ----------
    {
        const int dg = t & 3;            // dim group (8 dims)
        const int kg = (t >> 2) & 15;    // split-k group
        const int rg = t >> 6;           // row group (4 rows)
        float acc[4][8] = {};

        for (int vj0 = 0; vj0 < NNN; vj0 += 256) {
            __syncthreads();
            #pragma unroll
            for (int r = 0; r < 8; r++) {
                int idx = t + r * 256;
                int c = idx >> 3, f4 = idx & 7;
                float4 v4 = *(const float4*)(V + (long long)(vj0 + c) * DHH + f4 * 4);
                float* p = vt + c * 33 + f4 * 4;
                p[0] = v4.x; p[1] = v4.y; p[2] = v4.z; p[3] = v4.w;
            }
            __syncthreads();

            #pragma unroll
            for (int i = 0; i < 16; i++) {
                int kl = i * 16 + kg;
                float s0 = S[(rg * 4 + 0) * SS + vj0 + kl];
                float s1 = S[(rg * 4 + 1) * SS + vj0 + kl];
                float s2 = S[(rg * 4 + 2) * SS + vj0 + kl];
                float s3 = S[(rg * 4 + 3) * SS + vj0 + kl];
                const float* vp = vt + kl * 33 + dg * 8;
                #pragma unroll
                for (int j = 0; j < 8; j++) {
                    float vv = vp[j];
                    acc[0][j] += s0 * vv;
                    acc[1][j] += s1 * vv;
                    acc[2][j] += s2 * vv;
                    acc[3][j] += s3 * vv;
                }
            }
        }
        __syncthreads();   // vt dead; region becomes red[]
        #pragma unroll
        for (int r = 0; r < 4; r++)
            #pragma unroll
            for (int j = 0; j < 8; j++)
                red[kg * 513 + (rg * 4 + r) * 32 + dg * 8 + j] = acc[r][j];
        __syncthreads();

        const int b = bh >> 3, h = bh & 7;
        #pragma unroll
        for (int s = 0; s < 2; s++) {
            int out = t + s * 256;          // 512 outputs
            int row = out >> 5, d = out & 31;
            float sum = 0.f;
            #pragma unroll
            for (int k2 = 0; k2 < 16; k2++) sum += red[k2 * 513 + out];
            sum *= rinv[row];
            g_comb[((long long)b * NNN + i0 + row) * CCC + h * DHH + d] = sum;
        }
    }
}

// ============================================================
// Kernel 3: local window attention, accumulates into g_comb
// ============================================================
__global__ __launch_bounds__(128) void local_attn_kernel() {
    __shared__ float ql[16 * 33], kl[16 * 33], vl[16 * 33], sl[16 * 17];
    const int t  = threadIdx.x;
    const int w  = blockIdx.x;
    const int bh = blockIdx.y;
    const float* Qp = g_qkv + ((long long)bh * NNN + w * WINW) * DHH;
    const float* Kp = g_qkv + (((long long)BB * HHH + bh) * NNN + w * WINW) * DHH;
    const float* Vp = g_qkv + (((long long)2 * BB * HHH + bh) * NNN + w * WINW) * DHH;

    #pragma unroll
    for (int r = 0; r < 4; r++) {
        int idx = t + r * 128;
        int i = idx >> 5, d = idx & 31;
        ql[i * 33 + d] = Qp[idx];
        kl[i * 33 + d] = Kp[idx];
        vl[i * 33 + d] = Vp[idx];
    }
    __syncthreads();
    #pragma unroll
    for (int r = 0; r < 2; r++) {
        int p = t + r * 128;
        int i = p >> 4, j = p & 15;
        float a = 0.f;
        #pragma unroll
        for (int d = 0; d < 32; d++) a += ql[i * 33 + d] * kl[j * 33 + d];
        sl[i * 17 + j] = a * SCALE;
    }
    __syncthreads();
    if (t < 16) {
        float m = -1e30f;
        #pragma unroll
        for (int j = 0; j < 16; j++) m = fmaxf(m, sl[t * 17 + j]);
        float s = 0.f;
        #pragma unroll
        for (int j = 0; j < 16; j++) { float e = __expf(sl[t * 17 + j] - m); sl[t * 17 + j] = e; s += e; }
        float inv = 1.0f / s;
        #pragma unroll
        for (int j = 0; j < 16; j++) sl[t * 17 + j] *= inv;
    }
    __syncthreads();
    const int b = bh >> 3, h = bh & 7;
    float* cb = g_comb + ((long long)b * NNN + w * WINW) * CCC + h * DHH;
    #pragma unroll
    for (int r = 0; r < 4; r++) {
        int p = t + r * 128;
        int i = p >> 5, d = p & 31;
        float a = 0.f;
        #pragma unroll
        for (int j = 0; j < 16; j++) a += sl[i * 17 + j] * vl[j * 33 + d];
        cb[(long long)i * CCC + d] += a;
    }
}

// ============================================================
// Kernel 4: output projection.  g_comb[8192,256] @ Wp[256,256] + b -> out
// ============================================================
__global__ __launch_bounds__(256) void proj_gemm_kernel(const float* __restrict__ W,
                                                        const float* __restrict__ bias,
                                                        float* __restrict__ out) {
    __shared__ float Xs[16 * 68];
    __shared__ float Ws[16 * 64];
    const int t  = threadIdx.x;
    const int tx = t & 15, ty = t >> 4;
    const int m0 = blockIdx.y * 64;
    const int n0 = blockIdx.x * 64;

    float acc[4][4] = {};
    for (int k0 = 0; k0 < CCC; k0 += 16) {
        {
            int kk = t & 15, mloc = t >> 4;
            #pragma unroll
            for (int r = 0; r < 4; r++) {
                int m = mloc + r * 16;
                Xs[kk * 68 + m] = g_comb[(long long)(m0 + m) * CCC + k0 + kk];
            }
        }
        {
            int nn = t & 63, kk = t >> 6;
            #pragma unroll
            for (int r = 0; r < 4; r++)
                Ws[(kk + r * 4) * 64 + nn] = W[(long long)(k0 + kk + r * 4) * CCC + n0 + nn];
        }
        __syncthreads();
        #pragma unroll
        for (int kk = 0; kk < 16; kk++) {
            float4 a = *(const float4*)(Xs + kk * 68 + ty * 4);
            float4 b = *(const float4*)(Ws + kk * 64 + tx * 4);
            acc[0][0] += a.x * b.x; acc[0][1] += a.x * b.y; acc[0][2] += a.x * b.z; acc[0][3] += a.x * b.w;
            acc[1][0] += a.y * b.x; acc[1][1] += a.y * b.y; acc[1][2] += a.y * b.z; acc[1][3] += a.y * b.w;
            acc[2][0] += a.z * b.x; acc[2][1] += a.z * b.y; acc[2][2] += a.z * b.z; acc[2][3] += a.z * b.w;
            acc[3][0] += a.w * b.x; acc[3][1] += a.w * b.y; acc[3][2] += a.w * b.z; acc[3][3] += a.w * b.w;
        }
        __syncthreads();
    }
    #pragma unroll
    for (int ii = 0; ii < 4; ii++) {
        int row = m0 + ty * 4 + ii;
        #pragma unroll
        for (int jj = 0; jj < 4; jj++) {
            int col = n0 + tx * 4 + jj;
            out[(long long)row * CCC + col] = acc[ii][jj] + bias[col];
        }
    }
}

// ============================================================
extern "C" void kernel_launch(void* const* d_in, const int* in_sizes, int n_in,
                              void* d_out, int out_size) {
    const float* x     = (const float*)d_in[0];
    const float* Wqkv  = (const float*)d_in[1];
    const float* Wproj = (const float*)d_in[2];
    const float* bproj = (const float*)d_in[3];
    float* out   = (float*)d_out;
    float* out_w = out + (long long)BB * NNN * CCC;

    cudaFuncSetAttribute(attn_global_kernel,
                         cudaFuncAttributeMaxDynamicSharedMemorySize, ATTN_SMEM);

    qkv_gemm_kernel<<<dim3(12, 128), 256>>>(x, Wqkv);
    attn_global_kernel<<<dim3(NNN / 16, BB * HHH), 256, ATTN_SMEM>>>(out_w);
    local_attn_kernel<<<dim3(NNN / WINW, BB * HHH), 128>>>();
    proj_gemm_kernel<<<dim3(CCC / 64, (BB * NNN) / 64), 256>>>(Wproj, bproj, out);
}

// round 5
// speedup vs baseline: 2.2390x; 1.1004x over previous
#include <cuda_runtime.h>

#define BB   4
#define NNN  2048
#define CCC  256
#define HHH  8
#define DHH  32
#define WINW 16
#define SCALE 0.17677669529663687f   // 32^-0.5

typedef unsigned long long u64;

__device__ __forceinline__ u64 fma2(u64 a, u64 b, u64 c) {
    u64 d;
    asm("fma.rn.f32x2 %0, %1, %2, %3;" : "=l"(d) : "l"(a), "l"(b), "l"(c));
    return d;
}
__device__ __forceinline__ u64 pack2(float lo, float hi) {
    u64 d;
    asm("mov.b64 %0, {%1, %2};" : "=l"(d) : "f"(lo), "f"(hi));
    return d;
}
__device__ __forceinline__ float pairsum(u64 p) {
    float lo, hi;
    asm("mov.b64 {%0, %1}, %2;" : "=f"(lo), "=f"(hi) : "l"(p));
    return lo + hi;
}

// -------- scratch (device globals; no allocations allowed) --------
__device__ float g_qkv[3LL * BB * HHH * NNN * DHH];   // [3][B][H][N][32]  24 MB
__device__ float g_comb[(long long)BB * NNN * CCC];   // [B][N][C]          8 MB

// ============================================================
// Kernel 1: QKV GEMM.  X[8192,256] @ W[256,768] -> scatter to g_qkv
// ============================================================
__global__ __launch_bounds__(256) void qkv_gemm_kernel(const float* __restrict__ X,
                                                       const float* __restrict__ W) {
    __shared__ float Xs[16 * 68];
    __shared__ float Ws[16 * 64];
    const int t  = threadIdx.x;
    const int tx = t & 15, ty = t >> 4;
    const int m0 = blockIdx.y * 64;
    const int n0 = blockIdx.x * 64;

    float acc[4][4] = {};

    for (int k0 = 0; k0 < CCC; k0 += 16) {
        {
            int kk = t & 15, mloc = t >> 4;
            #pragma unroll
            for (int r = 0; r < 4; r++) {
                int m = mloc + r * 16;
                Xs[kk * 68 + m] = X[(long long)(m0 + m) * CCC + k0 + kk];
            }
        }
        {
            int nn = t & 63, kk = t >> 6;
            #pragma unroll
            for (int r = 0; r < 4; r++)
                Ws[(kk + r * 4) * 64 + nn] = W[(long long)(k0 + kk + r * 4) * 768 + n0 + nn];
        }
        __syncthreads();
        #pragma unroll
        for (int kk = 0; kk < 16; kk++) {
            float4 a = *(const float4*)(Xs + kk * 68 + ty * 4);
            float4 b = *(const float4*)(Ws + kk * 64 + tx * 4);
            acc[0][0] += a.x * b.x; acc[0][1] += a.x * b.y; acc[0][2] += a.x * b.z; acc[0][3] += a.x * b.w;
            acc[1][0] += a.y * b.x; acc[1][1] += a.y * b.y; acc[1][2] += a.y * b.z; acc[1][3] += a.y * b.w;
            acc[2][0] += a.z * b.x; acc[2][1] += a.z * b.y; acc[2][2] += a.z * b.z; acc[2][3] += a.z * b.w;
            acc[3][0] += a.w * b.x; acc[3][1] += a.w * b.y; acc[3][2] += a.w * b.z; acc[3][3] += a.w * b.w;
        }
        __syncthreads();
    }
    #pragma unroll
    for (int ii = 0; ii < 4; ii++) {
        int row = m0 + ty * 4 + ii;
        int b   = row >> 11;
        int n   = row & 2047;
        #pragma unroll
        for (int jj = 0; jj < 4; jj++) {
            int col = n0 + tx * 4 + jj;
            int t3  = col >> 8;
            int rem = col & 255;
            int h   = rem >> 5;
            int d   = rem & 31;
            g_qkv[((((long long)t3 * BB + b) * HHH + h) * NNN + n) * DHH + d] = acc[ii][jj];
        }
    }
}

// ============================================================
// Kernel 2: fused global attention per (b,h, 16-row block)
// f32x2 packed math in both GEMM phases.
// smem (floats):
//   S[16][2052]                 0      .. 32832
//   qs: 16 rows x stride 34     32832  (f32x2 pairs over d, scale folded)
//   rinv[16]                    33376
//   ks: 512 x 34                33392  (aliases vt 256x34, red 16x514)
// ============================================================
#define SS        2052
#define QS_OFF    (16 * SS)                 // 32832
#define RINV_OFF  (QS_OFF + 16 * 34)        // 33376
#define KS_OFF    (RINV_OFF + 16)           // 33392
#define ATTN_FLOATS (KS_OFF + 512 * 34)     // 50800
#define ATTN_SMEM (ATTN_FLOATS * 4)         // 203200 bytes

__global__ __launch_bounds__(256) void attn_global_kernel(float* __restrict__ out_w) {
    extern __shared__ float sm[];
    float* S    = sm;
    float* qs   = sm + QS_OFF;     // row stride 34 floats (17 f2-pairs over d)
    float* rinv = sm + RINV_OFF;
    float* ks   = sm + KS_OFF;     // ks[c][d], stride 34
    float* vt   = sm + KS_OFF;     // vt[c][d], stride 34 (alias)
    float* red  = sm + KS_OFF;     // red[kg][514]       (alias, after vt dead)

    const int t  = threadIdx.x;
    const int bh = blockIdx.y;
    const int i0 = blockIdx.x * 16;
    const float* Q = g_qkv + (long long)bh * NNN * DHH;
    const float* K = g_qkv + ((long long)BB * HHH + bh) * NNN * DHH;
    const float* V = g_qkv + ((long long)2 * BB * HHH + bh) * NNN * DHH;

    // ---- build packed q (real pairs over d, scale folded) ----
    {
        int r = t >> 4, d2 = t & 15;
        float2 qv = *(const float2*)(Q + (long long)(i0 + r) * DHH + 2 * d2);
        *(float2*)(qs + r * 34 + 2 * d2) = make_float2(qv.x * SCALE, qv.y * SCALE);
    }

    // ---------- Phase 1: S = q.K^T  (tiles of 512 cols, f32x2 over d) ----------
    {
        const int cg = t & 63, rg = t >> 6;
        for (int kj0 = 0; kj0 < NNN; kj0 += 512) {
            __syncthreads();
            // load K tile: ks[c][d], stride 34; float2 halves of each float4 (conflict-free STS.64)
            #pragma unroll
            for (int r = 0; r < 16; r++) {
                int idx = t + r * 256;
                int c = idx >> 3, f4 = idx & 7;
                float4 k4 = *(const float4*)(K + (long long)(kj0 + c) * DHH + f4 * 4);
                *(float2*)(ks + c * 34 + f4 * 4)     = make_float2(k4.x, k4.y);
                *(float2*)(ks + c * 34 + f4 * 4 + 2) = make_float2(k4.z, k4.w);
            }
            __syncthreads();

            u64 acc2[4][8] = {};
            #pragma unroll
            for (int d2 = 0; d2 < 16; d2++) {
                u64 q2[4];
                #pragma unroll
                for (int r = 0; r < 4; r++)
                    q2[r] = *(const u64*)(qs + (rg * 4 + r) * 34 + 2 * d2);   // broadcast
                u64 k2[8];
                #pragma unroll
                for (int cc = 0; cc < 8; cc++)
                    k2[cc] = *(const u64*)(ks + (cg + 64 * cc) * 34 + 2 * d2);
                #pragma unroll
                for (int r = 0; r < 4; r++)
                    #pragma unroll
                    for (int cc = 0; cc < 8; cc++)
                        acc2[r][cc] = fma2(q2[r], k2[cc], acc2[r][cc]);
            }
            #pragma unroll
            for (int r = 0; r < 4; r++)
                #pragma unroll
                for (int cc = 0; cc < 8; cc++)
                    S[(rg * 4 + r) * SS + kj0 + cg + 64 * cc] = pairsum(acc2[r][cc]);
        }
    }
    __syncthreads();

    // ---------- Phase 2: softmax stats; S := e (unnormalized) ----------
    {
        int row = t >> 4, lane = t & 15;
        float* Sr = S + row * SS;
        float m = -1e30f;
        #pragma unroll 8
        for (int i = 0; i < 32; i++) {
            float4 v = *(const float4*)(Sr + i * 64 + lane * 4);
            m = fmaxf(m, fmaxf(fmaxf(v.x, v.y), fmaxf(v.z, v.w)));
        }
        #pragma unroll
        for (int o = 8; o; o >>= 1) m = fmaxf(m, __shfl_xor_sync(0xffffffffu, m, o, 16));
        float ssum = 0.f;
        #pragma unroll 8
        for (int i = 0; i < 32; i++) {
            float4 v = *(float4*)(Sr + i * 64 + lane * 4);
            v.x = __expf(v.x - m); v.y = __expf(v.y - m);
            v.z = __expf(v.z - m); v.w = __expf(v.w - m);
            *(float4*)(Sr + i * 64 + lane * 4) = v;
            ssum += (v.x + v.y) + (v.z + v.w);
        }
        #pragma unroll
        for (int o = 8; o; o >>= 1) ssum += __shfl_xor_sync(0xffffffffu, ssum, o, 16);
        if (lane == 0) rinv[row] = 1.0f / ssum;
    }
    __syncthreads();

    // ---------- Phase 2b: write normalized weights to gmem (float4) ----------
    {
        float* wbase = out_w + (long long)bh * NNN * NNN + (long long)i0 * NNN;
        for (int i = 0; i < 16; i++) {
            float inv = rinv[i];
            #pragma unroll
            for (int r = 0; r < 2; r++) {
                int idx = t + r * 256;
                float4 v = *(const float4*)(S + i * SS + idx * 4);
                v.x *= inv; v.y *= inv; v.z *= inv; v.w *= inv;
                *(float4*)(wbase + (long long)i * NNN + idx * 4) = v;
            }
        }
    }

    // ---------- Phase 3: O = e.V  (16-way split-k, f32x2 over output dims) ----------
    {
        const int kg  = t & 15;          // split-k group
        const int d2g = (t >> 4) & 7;    // 4 output dims (2 f2-pairs)
        const int rg  = t >> 7;          // 8 rows
        u64 acc2[8][2] = {};

        for (int vj0 = 0; vj0 < NNN; vj0 += 256) {
            __syncthreads();
            #pragma unroll
            for (int r = 0; r < 8; r++) {
                int idx = t + r * 256;
                int c = idx >> 3, f4 = idx & 7;
                float4 v4 = *(const float4*)(V + (long long)(vj0 + c) * DHH + f4 * 4);
                *(float2*)(vt + c * 34 + f4 * 4)     = make_float2(v4.x, v4.y);
                *(float2*)(vt + c * 34 + f4 * 4 + 2) = make_float2(v4.z, v4.w);
            }
            __syncthreads();

            #pragma unroll 4
            for (int i = 0; i < 16; i++) {
                int kl = i * 16 + kg;
                u64 v2a = *(const u64*)(vt + kl * 34 + d2g * 4);
                u64 v2b = *(const u64*)(vt + kl * 34 + d2g * 4 + 2);
                #pragma unroll
                for (int rr = 0; rr < 8; rr++) {
                    float s = S[(rg * 8 + rr) * SS + vj0 + kl];
                    u64 sp = pack2(s, s);
                    acc2[rr][0] = fma2(sp, v2a, acc2[rr][0]);
                    acc2[rr][1] = fma2(sp, v2b, acc2[rr][1]);
                }
            }
        }
        __syncthreads();   // vt dead; region becomes red[]
        #pragma unroll
        for (int rr = 0; rr < 8; rr++) {
            *(u64*)(red + kg * 514 + (rg * 8 + rr) * 32 + d2g * 4)     = acc2[rr][0];
            *(u64*)(red + kg * 514 + (rg * 8 + rr) * 32 + d2g * 4 + 2) = acc2[rr][1];
        }
        __syncthreads();

        const int b = bh >> 3, h = bh & 7;
        #pragma unroll
        for (int s2 = 0; s2 < 2; s2++) {
            int out = t + s2 * 256;          // 512 outputs
            int row = out >> 5, d = out & 31;
            float sum = 0.f;
            #pragma unroll
            for (int k2 = 0; k2 < 16; k2++) sum += red[k2 * 514 + out];
            sum *= rinv[row];
            g_comb[((long long)b * NNN + i0 + row) * CCC + h * DHH + d] = sum;
        }
    }
}

// ============================================================
// Kernel 3: local window attention, accumulates into g_comb
// ============================================================
__global__ __launch_bounds__(128) void local_attn_kernel() {
    __shared__ float ql[16 * 33], kl[16 * 33], vl[16 * 33], sl[16 * 17];
    const int t  = threadIdx.x;
    const int w  = blockIdx.x;
    const int bh = blockIdx.y;
    const float* Qp = g_qkv + ((long long)bh * NNN + w * WINW) * DHH;
    const float* Kp = g_qkv + (((long long)BB * HHH + bh) * NNN + w * WINW) * DHH;
    const float* Vp = g_qkv + (((long long)2 * BB * HHH + bh) * NNN + w * WINW) * DHH;

    #pragma unroll
    for (int r = 0; r < 4; r++) {
        int idx = t + r * 128;
        int i = idx >> 5, d = idx & 31;
        ql[i * 33 + d] = Qp[idx];
        kl[i * 33 + d] = Kp[idx];
        vl[i * 33 + d] = Vp[idx];
    }
    __syncthreads();
    #pragma unroll
    for (int r = 0; r < 2; r++) {
        int p = t + r * 128;
        int i = p >> 4, j = p & 15;
        float a = 0.f;
        #pragma unroll
        for (int d = 0; d < 32; d++) a += ql[i * 33 + d] * kl[j * 33 + d];
        sl[i * 17 + j] = a * SCALE;
    }
    __syncthreads();
    if (t < 16) {
        float m = -1e30f;
        #pragma unroll
        for (int j = 0; j < 16; j++) m = fmaxf(m, sl[t * 17 + j]);
        float s = 0.f;
        #pragma unroll
        for (int j = 0; j < 16; j++) { float e = __expf(sl[t * 17 + j] - m); sl[t * 17 + j] = e; s += e; }
        float inv = 1.0f / s;
        #pragma unroll
        for (int j = 0; j < 16; j++) sl[t * 17 + j] *= inv;
    }
    __syncthreads();
    const int b = bh >> 3, h = bh & 7;
    float* cb = g_comb + ((long long)b * NNN + w * WINW) * CCC + h * DHH;
    #pragma unroll
    for (int r = 0; r < 4; r++) {
        int p = t + r * 128;
        int i = p >> 5, d = p & 31;
        float a = 0.f;
        #pragma unroll
        for (int j = 0; j < 16; j++) a += sl[i * 17 + j] * vl[j * 33 + d];
        cb[(long long)i * CCC + d] += a;
    }
}

// ============================================================
// Kernel 4: output projection.  g_comb[8192,256] @ Wp[256,256] + b -> out
// ============================================================
__global__ __launch_bounds__(256) void proj_gemm_kernel(const float* __restrict__ W,
                                                        const float* __restrict__ bias,
                                                        float* __restrict__ out) {
    __shared__ float Xs[16 * 68];
    __shared__ float Ws[16 * 64];
    const int t  = threadIdx.x;
    const int tx = t & 15, ty = t >> 4;
    const int m0 = blockIdx.y * 64;
    const int n0 = blockIdx.x * 64;

    float acc[4][4] = {};
    for (int k0 = 0; k0 < CCC; k0 += 16) {
        {
            int kk = t & 15, mloc = t >> 4;
            #pragma unroll
            for (int r = 0; r < 4; r++) {
                int m = mloc + r * 16;
                Xs[kk * 68 + m] = g_comb[(long long)(m0 + m) * CCC + k0 + kk];
            }
        }
        {
            int nn = t & 63, kk = t >> 6;
            #pragma unroll
            for (int r = 0; r < 4; r++)
                Ws[(kk + r * 4) * 64 + nn] = W[(long long)(k0 + kk + r * 4) * CCC + n0 + nn];
        }
        __syncthreads();
        #pragma unroll
        for (int kk = 0; kk < 16; kk++) {
            float4 a = *(const float4*)(Xs + kk * 68 + ty * 4);
            float4 b = *(const float4*)(Ws + kk * 64 + tx * 4);
            acc[0][0] += a.x * b.x; acc[0][1] += a.x * b.y; acc[0][2] += a.x * b.z; acc[0][3] += a.x * b.w;
            acc[1][0] += a.y * b.x; acc[1][1] += a.y * b.y; acc[1][2] += a.y * b.z; acc[1][3] += a.y * b.w;
            acc[2][0] += a.z * b.x; acc[2][1] += a.z * b.y; acc[2][2] += a.z * b.z; acc[2][3] += a.z * b.w;
            acc[3][0] += a.w * b.x; acc[3][1] += a.w * b.y; acc[3][2] += a.w * b.z; acc[3][3] += a.w * b.w;
        }
        __syncthreads();
    }
    #pragma unroll
    for (int ii = 0; ii < 4; ii++) {
        int row = m0 + ty * 4 + ii;
        #pragma unroll
        for (int jj = 0; jj < 4; jj++) {
            int col = n0 + tx * 4 + jj;
            out[(long long)row * CCC + col] = acc[ii][jj] + bias[col];
        }
    }
}

// ============================================================
extern "C" void kernel_launch(void* const* d_in, const int* in_sizes, int n_in,
                              void* d_out, int out_size) {
    const float* x     = (const float*)d_in[0];
    const float* Wqkv  = (const float*)d_in[1];
    const float* Wproj = (const float*)d_in[2];
    const float* bproj = (const float*)d_in[3];
    float* out   = (float*)d_out;
    float* out_w = out + (long long)BB * NNN * CCC;

    cudaFuncSetAttribute(attn_global_kernel,
                         cudaFuncAttributeMaxDynamicSharedMemorySize, ATTN_SMEM);

    qkv_gemm_kernel<<<dim3(12, 128), 256>>>(x, Wqkv);
    attn_global_kernel<<<dim3(NNN / 16, BB * HHH), 256, ATTN_SMEM>>>(out_w);
    local_attn_kernel<<<dim3(NNN / WINW, BB * HHH), 128>>>();
    proj_gemm_kernel<<<dim3(CCC / 64, (BB * NNN) / 64), 256>>>(Wproj, bproj, out);
}